// round 13
// baseline (speedup 1.0000x reference)
#include <cuda_runtime.h>

#define G_N 8192
#define IMG_W 512
#define IMG_H 512
#define TILE 16
#define TX_N (IMG_W / TILE)       // 32
#define TY_N (IMG_H / TILE)       // 32
#define N_TILES (TX_N * TY_N)     // 1024
#define NWORDS (G_N / 32)         // 256 bitmap words per tile
#define TPB 256
#define CH 512                    // raster staging chunk (entries)
#define NBUCK 16384               // key >> 18 (sign0 + exp8 + mant5)

// Sorted (by depth) gaussian data, raster-ready layout.
__device__ float4 d_A[G_N];              // mx, my, 0.5*a, b
__device__ float4 d_B[G_N];              // 0.5*c, sigma_max=ln(255*op), op, col.r
__device__ float2 d_C[G_N];              // col.g, col.b
__device__ float4 d_bbox[G_N];           // x0, y0, x1, y1
// Per-tile rank bitmaps: bit r set => sorted gaussian r overlaps the tile.
__device__ unsigned d_bits[N_TILES * NWORDS];   // 1 MB
// Bucket-rank scratch. Zero at module load; raster re-zeroes hist/cur each
// launch so graph replays always start from zeros (deterministic).
__device__ unsigned d_hist[NBUCK];
__device__ unsigned d_cur [NBUCK];
__device__ unsigned d_off [NBUCK];
__device__ uint2    d_bk  [G_N];         // bucket-ordered (key, orig index)

// ---------------------------------------------------------------------------
// S1: bitmap clear + bucket histogram. 128 blocks x 256 = 32768 threads.
// ---------------------------------------------------------------------------
__global__ __launch_bounds__(TPB) void hist_kernel(const float* __restrict__ depths)
{
    const int tid = blockIdx.x * TPB + threadIdx.x;    // 0..32767
    uint4* bits4 = (uint4*)d_bits;
    bits4[tid]         = make_uint4(0u, 0u, 0u, 0u);   // 65536 uint4 total
    bits4[tid + 32768] = make_uint4(0u, 0u, 0u, 0u);
    if (tid < G_N) {
        const unsigned k = __float_as_uint(depths[tid]);   // depths>0: monotone
        atomicAdd(&d_hist[k >> 18], 1u);
    }
}

// ---------------------------------------------------------------------------
// S2: exclusive prefix sum of d_hist -> d_off. One block, 512 threads,
// 32 buckets per thread.
// ---------------------------------------------------------------------------
__global__ __launch_bounds__(512) void scan_kernel()
{
    __shared__ unsigned s_wsum[16];
    const int t = threadIdx.x, lane = t & 31, warp = t >> 5;
    const int base = t * 32;

    unsigned s = 0;
#pragma unroll
    for (int k = 0; k < 32; ++k) s += d_hist[base + k];

    unsigned incl = s;
#pragma unroll
    for (int o = 1; o < 32; o <<= 1) {
        const unsigned v = __shfl_up_sync(0xffffffffu, incl, o);
        if (lane >= o) incl += v;
    }
    if (lane == 31) s_wsum[warp] = incl;
    __syncthreads();
    if (warp == 0 && lane < 16) {
        unsigned w = s_wsum[lane];
#pragma unroll
        for (int o = 1; o < 16; o <<= 1) {
            const unsigned v = __shfl_up_sync(0xffffu, w, o);
            if (lane >= o) w += v;
        }
        s_wsum[lane] = w;
    }
    __syncthreads();
    unsigned run = incl - s + (warp > 0 ? s_wsum[warp - 1] : 0u);   // exclusive base
#pragma unroll
    for (int k = 0; k < 32; ++k) {
        const unsigned h = d_hist[base + k];
        d_off[base + k] = run;
        run += h;
    }
}

// ---------------------------------------------------------------------------
// S3: scatter (key, idx) into bucket-ordered slots. Slot order within a
// bucket is nondeterministic (atomic), but ranks are computed in S4 by
// comparison over the whole bucket -> final result is deterministic.
// ---------------------------------------------------------------------------
__global__ __launch_bounds__(TPB) void scatter_kernel(const float* __restrict__ depths)
{
    const int i = blockIdx.x * TPB + threadIdx.x;      // 0..8191
    const unsigned k = __float_as_uint(depths[i]);
    const unsigned b = k >> 18;
    const unsigned slot = d_off[b] + atomicAdd(&d_cur[b], 1u);
    d_bk[slot] = make_uint2(k, (unsigned)i);
}

// ---------------------------------------------------------------------------
// S4: rank within bucket (composite comparator (key, index) reproduces
// argsort(stable=True) exactly) + gather into sorted SoA + bbox.
// ---------------------------------------------------------------------------
__global__ __launch_bounds__(TPB) void rank_gather_kernel(
    const float* __restrict__ means2d,
    const float* __restrict__ conics,
    const float* __restrict__ colors,
    const float* __restrict__ opac,
    const float* __restrict__ depths)
{
    const int i = blockIdx.x * TPB + threadIdx.x;      // 0..8191
    const unsigned ki = __float_as_uint(depths[i]);
    const unsigned bu = ki >> 18;
    const unsigned o  = d_off[bu];
    const unsigned n  = d_hist[bu];

    int r = (int)o;
    for (unsigned u = 0; u < n; ++u) {
        const uint2 e = d_bk[o + u];
        r += (e.x < ki) || ((e.x == ki) && ((int)e.y < i));
    }

    const float mx = means2d[2 * i];
    const float my = means2d[2 * i + 1];
    const float a  = conics[3 * i];
    const float b  = conics[3 * i + 1];
    const float c  = conics[3 * i + 2];
    const float op = opac[i];

    // alpha = op*exp(-sigma) >= 1/255  <=>  sigma <= ln(255*op) = smax
    const float smax = logf(op * 255.0f);
    const float det  = a * c - b * b;

    d_A[r] = make_float4(mx, my, 0.5f * a, b);
    d_B[r] = make_float4(0.5f * c, smax, op, colors[3 * i]);
    d_C[r] = make_float2(colors[3 * i + 1], colors[3 * i + 2]);

    float4 bb;
    if (smax > 0.0f && det > 0.0f) {
        const float rx = sqrtf(fmaxf(0.0f, 2.0f * smax * c / det)) * 1.001f + 0.01f;
        const float ry = sqrtf(fmaxf(0.0f, 2.0f * smax * a / det)) * 1.001f + 0.01f;
        bb = make_float4(mx - rx, my - ry, mx + rx, my + ry);
    } else {
        bb = make_float4(1e9f, 1e9f, -1e9f, -1e9f);
    }
    d_bbox[r] = bb;
}

// ---------------------------------------------------------------------------
// Exact (conservative) ellipse-vs-rect: keep iff min over rect of
// sigma(p) = A2*dx^2 + b*dx*dy + C2*dy^2 is <= smax (+margin).
// ---------------------------------------------------------------------------
__device__ __forceinline__ bool ellipse_hits_rect(
    float mx, float my, float A2, float b, float C2, float smax,
    float X0, float X1, float Y0, float Y1)
{
    if (mx >= X0 && mx <= X1 && my >= Y0 && my <= Y1) return true;
    const float dx0 = X0 - mx, dx1 = X1 - mx;
    const float dy0 = Y0 - my, dy1 = Y1 - my;
    const float fy = __fdividef(-b, 2.0f * C2);
    const float fx = __fdividef(-b, 2.0f * A2);

    float q = 3.4e38f;
    {   const float y = fminf(fmaxf(fy * dx0, dy0), dy1);
        q = fminf(q, A2 * dx0 * dx0 + b * dx0 * y + C2 * y * y); }
    {   const float y = fminf(fmaxf(fy * dx1, dy0), dy1);
        q = fminf(q, A2 * dx1 * dx1 + b * dx1 * y + C2 * y * y); }
    {   const float x = fminf(fmaxf(fx * dy0, dx0), dx1);
        q = fminf(q, A2 * x * x + b * x * dy0 + C2 * dy0 * dy0); }
    {   const float x = fminf(fmaxf(fx * dy1, dx0), dx1);
        q = fminf(q, A2 * x * x + b * x * dy1 + C2 * dy1 * dy1); }
    return q <= smax + 1e-2f;    // conservative margin (over-keep only)
}

// ---------------------------------------------------------------------------
// Kernel: binning. 8 lanes per gaussian (4 gaussians/warp); lanes split the
// covered tile range. atomicOr is order-independent -> deterministic.
// ---------------------------------------------------------------------------
__global__ __launch_bounds__(TPB) void binning_kernel()
{
    const int r   = (blockIdx.x * (TPB / 32) + (threadIdx.x >> 5)) * 4
                  + ((threadIdx.x >> 3) & 3);
    const int sub = threadIdx.x & 7;

    const float4 bb = d_bbox[r];
    if (bb.x > bb.z) return;

    const int tx0 = max(0, __float2int_rd((bb.x - 0.5f) * (1.0f / 16.0f)));
    const int tx1 = min(TX_N - 1, __float2int_rd((bb.z - 0.5f) * (1.0f / 16.0f)));
    const int ty0 = max(0, __float2int_rd((bb.y - 0.5f) * (1.0f / 16.0f)));
    const int ty1 = min(TY_N - 1, __float2int_rd((bb.w - 0.5f) * (1.0f / 16.0f)));
    if (tx1 < tx0 || ty1 < ty0) return;

    const int W = tx1 - tx0 + 1;
    const int n = W * (ty1 - ty0 + 1);

    const float4 A = d_A[r];    // mx, my, a/2, b
    const float4 B = d_B[r];    // c/2, smax, op, col.r

    for (int t = sub; t < n; t += 8) {
        const int tx = tx0 + t % W;
        const int ty = ty0 + t / W;
        const float X0 = (float)(tx * TILE) + 0.5f;
        const float Y0 = (float)(ty * TILE) + 0.5f;
        if (ellipse_hits_rect(A.x, A.y, A.z, A.w, B.x, B.y,
                              X0, X0 + (float)(TILE - 1),
                              Y0, Y0 + (float)(TILE - 1))) {
            const int tile = ty * TX_N + tx;
            atomicOr(&d_bits[tile * NWORDS + (r >> 5)], 1u << (r & 31));
        }
    }
}

// ---------------------------------------------------------------------------
// Kernel: raster (identical to the 61.6us R11 version, plus: first 64 blocks
// re-zero d_hist/d_cur for the next graph replay).
// ---------------------------------------------------------------------------
__global__ __launch_bounds__(TPB) void raster_kernel(float* __restrict__ out)
{
    const int tileX = blockIdx.x, tileY = blockIdx.y;
    const int tileI = tileY * TX_N + tileX;
    const int tid   = threadIdx.x;
    const int warp  = tid >> 5, lane = tid & 31;
    const float px  = (float)(tileX * TILE + (tid & (TILE - 1))) + 0.5f;
    const float py  = (float)(tileY * TILE + (tid >> 4)) + 0.5f;

    // reset bucket scratch for next launch (runs after S1-S4 in this launch)
    if (tileI < NBUCK / TPB) {          // first 64 blocks
        d_hist[tileI * TPB + tid] = 0u;
        d_cur [tileI * TPB + tid] = 0u;
    }

    __shared__ unsigned short s_list[G_N];   // 16 KB
    __shared__ float4 s_A[CH];               // 8 KB
    __shared__ float4 s_B[CH];               // 8 KB
    __shared__ float2 s_C[CH];               // 4 KB
    __shared__ int s_wsum[8];
    __shared__ int s_cnt;

    // ---- Phase 1: build list ----
    const unsigned w = d_bits[tileI * NWORDS + tid];
    const int c = __popc(w);

    int incl = c;
#pragma unroll
    for (int o = 1; o < 32; o <<= 1) {
        const int v = __shfl_up_sync(0xffffffffu, incl, o);
        if (lane >= o) incl += v;
    }
    if (lane == 31) s_wsum[warp] = incl;
    __syncthreads();
    int base = 0;
#pragma unroll
    for (int k = 0; k < 8; ++k)
        if (k < warp) base += s_wsum[k];
    if (tid == 0) {
        int tot = 0;
#pragma unroll
        for (int k = 0; k < 8; ++k) tot += s_wsum[k];
        s_cnt = tot;
    }
    int ofs = base + incl - c;
    unsigned bits = w;
    const int rbase = tid << 5;
    while (bits) {
        const int rb = __ffs(bits) - 1;
        bits &= bits - 1;
        s_list[ofs++] = (unsigned short)(rbase + rb);
    }
    __syncthreads();
    const int cnt = s_cnt;

    // ---- Phase 2: chunked stage + composite ----
    float T = 1.0f;
    float aR = 0.0f, aG = 0.0f, aB = 0.0f;
    bool done = false;

    for (int c0 = 0; c0 < cnt; c0 += CH) {
        const int n = min(CH, cnt - c0);
        for (int k = tid; k < n; k += TPB) {
            const int r = s_list[c0 + k];
            s_A[k] = d_A[r];
            s_B[k] = d_B[r];
            s_C[k] = d_C[r];
        }
        __syncthreads();

#pragma unroll 1
        for (int j = 0; j < n; ++j) {
            if (!done) {
                const float4 A = s_A[j];       // broadcast LDS
                const float4 B = s_B[j];
                const float dx = px - A.x;
                const float dy = py - A.y;
                const float sg = fmaf(A.z * dx, dx,
                                 fmaf(B.x * dy, dy, A.w * dx * dy));
                if (sg >= 0.0f && sg <= B.y) {
                    const float2 C = s_C[j];
                    const float alpha = fminf(0.99f, B.z * __expf(-sg));
                    const float wgt = alpha * T;
                    aR += wgt * B.w; aG += wgt * C.x; aB += wgt * C.y;
                    T *= (1.0f - alpha);
                    done = (T < 1e-4f);
                }
            }
            if (__all_sync(0xffffffffu, done)) break;
        }
        __syncthreads();   // chunk consumed before restaging
    }

    float* o = out + ((size_t)(tileY * TILE + (tid >> 4)) * IMG_W
                      + (tileX * TILE + (tid & (TILE - 1)))) * 3;
    o[0] = aR;
    o[1] = aG;
    o[2] = aB;
}

// ---------------------------------------------------------------------------
extern "C" void kernel_launch(void* const* d_in, const int* in_sizes, int n_in,
                              void* d_out, int out_size)
{
    const float* means2d   = (const float*)d_in[0];
    const float* conics    = (const float*)d_in[1];
    const float* colors    = (const float*)d_in[2];
    const float* opacities = (const float*)d_in[3];
    const float* depths    = (const float*)d_in[4];
    float* out = (float*)d_out;

    hist_kernel<<<128, TPB>>>(depths);
    scan_kernel<<<1, 512>>>();
    scatter_kernel<<<G_N / TPB, TPB>>>(depths);
    rank_gather_kernel<<<G_N / TPB, TPB>>>(means2d, conics, colors, opacities, depths);
    binning_kernel<<<G_N / ((TPB / 32) * 4), TPB>>>();
    dim3 grid(TX_N, TY_N);
    raster_kernel<<<grid, TPB>>>(out);
}

// round 14
// speedup vs baseline: 1.5177x; 1.5177x over previous
#include <cuda_runtime.h>

#define G_N 8192
#define IMG_W 512
#define IMG_H 512
#define TILE 16
#define TX_N (IMG_W / TILE)       // 32
#define TY_N (IMG_H / TILE)       // 32
#define N_TILES (TX_N * TY_N)     // 1024
#define NWORDS (G_N / 32)         // 256 bitmap words per tile
#define TPB 256
#define RTPB 128                  // raster threads (2 px/thread, 16x16 tile)
#define CH 512                    // raster staging chunk (entries)
#define SORT_TPB 512
#define SORT_WPB (SORT_TPB / 32)  // 16 warps per block
#define SORT_GPW 2                // gaussians ranked per warp
#define SORT_BLOCKS (G_N / (SORT_WPB * SORT_GPW))   // 256
#define CLR_PER_BLK (N_TILES * NWORDS / 4 / SORT_BLOCKS)   // 256 uint4 per block

// Sorted (by depth) gaussian data, raster-ready layout.
__device__ float4 d_A[G_N];              // mx, my, 0.5*a, b
__device__ float4 d_B[G_N];              // 0.5*c, sigma_max=ln(255*op), op, col.r
__device__ float2 d_C[G_N];              // col.g, col.b
__device__ float4 d_bbox[G_N];           // x0, y0, x1, y1
// Per-tile rank bitmaps: bit r set => sorted gaussian r overlaps the tile.
__device__ unsigned d_bits[N_TILES * NWORDS];   // 1 MB

// ---------------------------------------------------------------------------
// Kernel 1: clear bitmaps + stable rank-sort by depth + gather + bbox.
// (R11 configuration, measured 16.8us — frozen.)
// 512 threads (16 warps), 2 gaussians per warp. Split comparator (i0, i0+1
// share boundary block since i0 is even):
//   j<i: kj<=ki ; j>i: kj<ki ; boundary t==tb: full composite.
// Reproduces argsort(stable=True) exactly (positive floats -> monotone bits).
// ---------------------------------------------------------------------------
__global__ __launch_bounds__(SORT_TPB) void sort_gather_kernel(
    const float* __restrict__ means2d,
    const float* __restrict__ conics,
    const float* __restrict__ colors,
    const float* __restrict__ opac,
    const float* __restrict__ depths)
{
    __shared__ uint2 s_k[G_N / 2];   // 32 KB
    const int tid  = threadIdx.x;
    const int warp = tid >> 5, lane = tid & 31;

    if (tid < CLR_PER_BLK)
        ((uint4*)d_bits)[blockIdx.x * CLR_PER_BLK + tid] = make_uint4(0u, 0u, 0u, 0u);

    const uint2* dbits = (const uint2*)depths;
    for (int j = tid; j < G_N / 2; j += SORT_TPB)
        s_k[j] = dbits[j];
    __syncthreads();

    const int i0 = (blockIdx.x * SORT_WPB + warp) * SORT_GPW;
    const unsigned* keys = (const unsigned*)s_k;
    const unsigned ki0 = keys[i0];
    const unsigned ki1 = keys[i0 + 1];
    const int tb = i0 >> 6;          // boundary iteration (same for both)

    int c0 = 0, c1 = 0;

#pragma unroll 4
    for (int t = 0; t < tb; ++t) {                 // j < i : kj <= ki
        const uint2 kj = s_k[t * 32 + lane];
        c0 += (kj.x <= ki0); c0 += (kj.y <= ki0);
        c1 += (kj.x <= ki1); c1 += (kj.y <= ki1);
    }
    {   // boundary iteration: full composite comparator
        const int j2 = tb * 32 + lane;
        const uint2 kj = s_k[j2];
        const int j = 2 * j2;
        c0 += (kj.x < ki0) || ((kj.x == ki0) && (j     < i0));
        c0 += (kj.y < ki0) || ((kj.y == ki0) && (j + 1 < i0));
        c1 += (kj.x < ki1) || ((kj.x == ki1) && (j     < i0 + 1));
        c1 += (kj.y < ki1) || ((kj.y == ki1) && (j + 1 < i0 + 1));
    }
#pragma unroll 4
    for (int t = tb + 1; t < G_N / 64; ++t) {      // j > i : kj < ki
        const uint2 kj = s_k[t * 32 + lane];
        c0 += (kj.x < ki0); c0 += (kj.y < ki0);
        c1 += (kj.x < ki1); c1 += (kj.y < ki1);
    }

    const int r0 = __reduce_add_sync(0xffffffffu, c0);
    const int r1 = __reduce_add_sync(0xffffffffu, c1);

    if (lane < SORT_GPW) {
        const int i = i0 + lane;
        const int r = (lane == 0) ? r0 : r1;

        const float mx = means2d[2 * i];
        const float my = means2d[2 * i + 1];
        const float a  = conics[3 * i];
        const float b  = conics[3 * i + 1];
        const float c  = conics[3 * i + 2];
        const float op = opac[i];

        // alpha = op*exp(-sigma) >= 1/255  <=>  sigma <= ln(255*op) = smax
        const float smax = logf(op * 255.0f);
        const float det  = a * c - b * b;

        d_A[r] = make_float4(mx, my, 0.5f * a, b);
        d_B[r] = make_float4(0.5f * c, smax, op, colors[3 * i]);
        d_C[r] = make_float2(colors[3 * i + 1], colors[3 * i + 2]);

        float4 bb;
        if (smax > 0.0f && det > 0.0f) {
            const float rx = sqrtf(fmaxf(0.0f, 2.0f * smax * c / det)) * 1.001f + 0.01f;
            const float ry = sqrtf(fmaxf(0.0f, 2.0f * smax * a / det)) * 1.001f + 0.01f;
            bb = make_float4(mx - rx, my - ry, mx + rx, my + ry);
        } else {
            bb = make_float4(1e9f, 1e9f, -1e9f, -1e9f);
        }
        d_bbox[r] = bb;
    }
}

// ---------------------------------------------------------------------------
// Exact (conservative) ellipse-vs-rect: keep iff min over rect of
// sigma(p) = A2*dx^2 + b*dx*dy + C2*dy^2 is <= smax (+margin).
// ---------------------------------------------------------------------------
__device__ __forceinline__ bool ellipse_hits_rect(
    float mx, float my, float A2, float b, float C2, float smax,
    float X0, float X1, float Y0, float Y1)
{
    if (mx >= X0 && mx <= X1 && my >= Y0 && my <= Y1) return true;
    const float dx0 = X0 - mx, dx1 = X1 - mx;
    const float dy0 = Y0 - my, dy1 = Y1 - my;
    const float fy = __fdividef(-b, 2.0f * C2);
    const float fx = __fdividef(-b, 2.0f * A2);

    float q = 3.4e38f;
    {   const float y = fminf(fmaxf(fy * dx0, dy0), dy1);
        q = fminf(q, A2 * dx0 * dx0 + b * dx0 * y + C2 * y * y); }
    {   const float y = fminf(fmaxf(fy * dx1, dy0), dy1);
        q = fminf(q, A2 * dx1 * dx1 + b * dx1 * y + C2 * y * y); }
    {   const float x = fminf(fmaxf(fx * dy0, dx0), dx1);
        q = fminf(q, A2 * x * x + b * x * dy0 + C2 * dy0 * dy0); }
    {   const float x = fminf(fmaxf(fx * dy1, dx0), dx1);
        q = fminf(q, A2 * x * x + b * x * dy1 + C2 * dy1 * dy1); }
    return q <= smax + 1e-2f;    // conservative margin (over-keep only)
}

// ---------------------------------------------------------------------------
// Kernel 2: binning. 8 lanes per gaussian (4 gaussians/warp); lanes split the
// covered tile range. atomicOr is order-independent -> deterministic.
// ---------------------------------------------------------------------------
__global__ __launch_bounds__(TPB) void binning_kernel()
{
    const int r   = (blockIdx.x * (TPB / 32) + (threadIdx.x >> 5)) * 4
                  + ((threadIdx.x >> 3) & 3);
    const int sub = threadIdx.x & 7;

    const float4 bb = d_bbox[r];
    if (bb.x > bb.z) return;

    const int tx0 = max(0, __float2int_rd((bb.x - 0.5f) * (1.0f / 16.0f)));
    const int tx1 = min(TX_N - 1, __float2int_rd((bb.z - 0.5f) * (1.0f / 16.0f)));
    const int ty0 = max(0, __float2int_rd((bb.y - 0.5f) * (1.0f / 16.0f)));
    const int ty1 = min(TY_N - 1, __float2int_rd((bb.w - 0.5f) * (1.0f / 16.0f)));
    if (tx1 < tx0 || ty1 < ty0) return;

    const int W = tx1 - tx0 + 1;
    const int n = W * (ty1 - ty0 + 1);

    const float4 A = d_A[r];    // mx, my, a/2, b
    const float4 B = d_B[r];    // c/2, smax, op, col.r

    for (int t = sub; t < n; t += 8) {
        const int tx = tx0 + t % W;
        const int ty = ty0 + t / W;
        const float X0 = (float)(tx * TILE) + 0.5f;
        const float Y0 = (float)(ty * TILE) + 0.5f;
        if (ellipse_hits_rect(A.x, A.y, A.z, A.w, B.x, B.y,
                              X0, X0 + (float)(TILE - 1),
                              Y0, Y0 + (float)(TILE - 1))) {
            const int tile = ty * TX_N + tx;
            atomicOr(&d_bits[tile * NWORDS + (r >> 5)], 1u << (r & 31));
        }
    }
}

// ---------------------------------------------------------------------------
// Kernel 3: raster. One 16x16 tile per block, 128 threads, 2 px/thread:
// pixels (x, ly) and (x, ly+8) share the column -> dx, (a/2)dx^2, b*dx
// computed once per rank for both pixels.
// Phase 1: bitmap -> compact uint16 rank list; each thread owns 2 consecutive
// bitmap words (uint2 load) so ascending-rank order is preserved.
// Phase 2: 512-entry chunks staged to smem, composite from broadcast LDS;
// warp exits via __all_sync when all its 64 pixels reach T < 1e-4 (exact).
// ---------------------------------------------------------------------------
__global__ __launch_bounds__(RTPB) void raster_kernel(float* __restrict__ out)
{
    const int tileX = blockIdx.x, tileY = blockIdx.y;
    const int tileI = tileY * TX_N + tileX;
    const int tid   = threadIdx.x;
    const int warp  = tid >> 5, lane = tid & 31;       // 4 warps
    const int lx    = tid & (TILE - 1);                // 0..15
    const int ly    = tid >> 4;                        // 0..7
    const float px  = (float)(tileX * TILE + lx) + 0.5f;
    const float py1 = (float)(tileY * TILE + ly) + 0.5f;

    __shared__ unsigned short s_list[G_N];   // 16 KB
    __shared__ float4 s_A[CH];               // 8 KB
    __shared__ float4 s_B[CH];               // 8 KB
    __shared__ float2 s_C[CH];               // 4 KB
    __shared__ int s_wsum[4];
    __shared__ int s_cnt;

    // ---- Phase 1: build list (2 consecutive words per thread) ----
    const uint2 w2 = ((const uint2*)(d_bits + tileI * NWORDS))[tid];
    const int c = __popc(w2.x) + __popc(w2.y);

    int incl = c;
#pragma unroll
    for (int o = 1; o < 32; o <<= 1) {
        const int v = __shfl_up_sync(0xffffffffu, incl, o);
        if (lane >= o) incl += v;
    }
    if (lane == 31) s_wsum[warp] = incl;
    __syncthreads();
    int base = 0;
#pragma unroll
    for (int k = 0; k < 4; ++k)
        if (k < warp) base += s_wsum[k];
    if (tid == 0)
        s_cnt = s_wsum[0] + s_wsum[1] + s_wsum[2] + s_wsum[3];
    int ofs = base + incl - c;
    {
        unsigned bits = w2.x;
        const int rb0 = (tid * 2) << 5;
        while (bits) {
            const int rb = __ffs(bits) - 1;
            bits &= bits - 1;
            s_list[ofs++] = (unsigned short)(rb0 + rb);
        }
        bits = w2.y;
        const int rb1 = (tid * 2 + 1) << 5;
        while (bits) {
            const int rb = __ffs(bits) - 1;
            bits &= bits - 1;
            s_list[ofs++] = (unsigned short)(rb1 + rb);
        }
    }
    __syncthreads();
    const int cnt = s_cnt;

    // ---- Phase 2: chunked stage + composite (2 px/thread) ----
    float T1 = 1.0f, T2 = 1.0f;
    float r1 = 0.f, g1 = 0.f, b1 = 0.f;
    float r2 = 0.f, g2 = 0.f, b2 = 0.f;
    bool done1 = false, done2 = false;

    for (int c0 = 0; c0 < cnt; c0 += CH) {
        const int n = min(CH, cnt - c0);
        for (int k = tid; k < n; k += RTPB) {
            const int r = s_list[c0 + k];
            s_A[k] = d_A[r];
            s_B[k] = d_B[r];
            s_C[k] = d_C[r];
        }
        __syncthreads();

#pragma unroll 1
        for (int j = 0; j < n; ++j) {
            if (!(done1 && done2)) {
                const float4 A = s_A[j];       // broadcast LDS
                const float4 B = s_B[j];
                const float dx  = px  - A.x;
                const float dy1 = py1 - A.y;
                const float dy2 = dy1 + 8.0f;
                const float u = A.z * dx * dx;     // (a/2)dx^2 (shared)
                const float v = A.w * dx;          // b*dx (shared)
                const float s1 = fmaf(B.x * dy1, dy1, fmaf(v, dy1, u));
                const float s2 = fmaf(B.x * dy2, dy2, fmaf(v, dy2, u));
                const bool p1 = (s1 >= 0.0f) && (s1 <= B.y) && !done1;
                const bool p2 = (s2 >= 0.0f) && (s2 <= B.y) && !done2;
                if (p1 | p2) {
                    const float2 C = s_C[j];
                    if (p1) {
                        const float alpha = fminf(0.99f, B.z * __expf(-s1));
                        const float wgt = alpha * T1;
                        r1 += wgt * B.w; g1 += wgt * C.x; b1 += wgt * C.y;
                        T1 *= (1.0f - alpha);
                        done1 = (T1 < 1e-4f);
                    }
                    if (p2) {
                        const float alpha = fminf(0.99f, B.z * __expf(-s2));
                        const float wgt = alpha * T2;
                        r2 += wgt * B.w; g2 += wgt * C.x; b2 += wgt * C.y;
                        T2 *= (1.0f - alpha);
                        done2 = (T2 < 1e-4f);
                    }
                }
            }
            if (__all_sync(0xffffffffu, done1 && done2)) break;
        }
        __syncthreads();   // chunk consumed before restaging
    }

    const int x  = tileX * TILE + lx;
    const int y1 = tileY * TILE + ly;
    float* o1 = out + ((size_t)y1 * IMG_W + x) * 3;
    o1[0] = r1; o1[1] = g1; o1[2] = b1;
    float* o2 = out + ((size_t)(y1 + 8) * IMG_W + x) * 3;
    o2[0] = r2; o2[1] = g2; o2[2] = b2;
}

// ---------------------------------------------------------------------------
extern "C" void kernel_launch(void* const* d_in, const int* in_sizes, int n_in,
                              void* d_out, int out_size)
{
    const float* means2d   = (const float*)d_in[0];
    const float* conics    = (const float*)d_in[1];
    const float* colors    = (const float*)d_in[2];
    const float* opacities = (const float*)d_in[3];
    const float* depths    = (const float*)d_in[4];
    float* out = (float*)d_out;

    sort_gather_kernel<<<SORT_BLOCKS, SORT_TPB>>>(means2d, conics, colors, opacities, depths);
    binning_kernel<<<G_N / ((TPB / 32) * 4), TPB>>>();
    dim3 grid(TX_N, TY_N);
    raster_kernel<<<grid, RTPB>>>(out);
}

// round 15
// speedup vs baseline: 1.5888x; 1.0468x over previous
#include <cuda_runtime.h>

#define G_N 8192
#define IMG_W 512
#define IMG_H 512
#define TILE 16
#define TX_N (IMG_W / TILE)       // 32
#define TY_N (IMG_H / TILE)       // 32
#define N_TILES (TX_N * TY_N)     // 1024
#define NWORDS (G_N / 32)         // 256 bitmap words per tile
#define TPB 256
#define CH 512                    // raster staging chunk (entries)
#define SORT_TPB 128              // 4 warps
#define SORT_GPW 8                // gaussians ranked per warp
#define SORT_BLOCKS (G_N / ((SORT_TPB / 32) * SORT_GPW))   // 256

// Sorted (by depth) gaussian data, raster-ready layout.
__device__ float4 d_A[G_N];              // mx, my, 0.5*a, b
__device__ float4 d_B[G_N];              // 0.5*c, sigma_max=ln(255*op), op, col.r
__device__ float2 d_C[G_N];              // col.g, col.b
__device__ float4 d_bbox[G_N];           // x0, y0, x1, y1
// Per-tile rank bitmaps: bit r set => sorted gaussian r overlaps the tile.
__device__ unsigned d_bits[N_TILES * NWORDS];   // 1 MB

// ---------------------------------------------------------------------------
// Kernel 1: clear bitmaps + stable rank-sort by depth + gather + bbox.
// LDG-streaming: no shared keys, no barrier. Each warp ranks 8 gaussians;
// lanes stream all keys via uint4 LDG (128 keys/warp/iter, 64 iters, high
// MLP -> L2-BW bound, not occupancy bound). i0 is 8-aligned so all 8 targets
// lie in boundary block tb = i0>>7. Split comparator:
//   t<tb: kj<=ki ; t>tb: kj<ki ; t==tb: full composite on (key, index).
// Reproduces argsort(stable=True) exactly (positive floats -> monotone bits).
// ---------------------------------------------------------------------------
__global__ __launch_bounds__(SORT_TPB) void sort_gather_kernel(
    const float* __restrict__ means2d,
    const float* __restrict__ conics,
    const float* __restrict__ colors,
    const float* __restrict__ opac,
    const float* __restrict__ depths)
{
    const int tid  = threadIdx.x;
    const int warp = tid >> 5, lane = tid & 31;

    // clear bitmaps: 256 blocks x 128 threads, 2 uint4 each = 65536 uint4
    {
        const int g = blockIdx.x * SORT_TPB + tid;
        uint4* bits4 = (uint4*)d_bits;
        bits4[g]         = make_uint4(0u, 0u, 0u, 0u);
        bits4[g + 32768] = make_uint4(0u, 0u, 0u, 0u);
    }

    const unsigned* ku = (const unsigned*)depths;
    const uint4*    k4 = (const uint4*)depths;

    const int i0 = (blockIdx.x * (SORT_TPB / 32) + warp) * SORT_GPW;
    unsigned ki[SORT_GPW];
#pragma unroll
    for (int g = 0; g < SORT_GPW; ++g) ki[g] = ku[i0 + g];   // broadcast loads

    const int tb = i0 >> 7;          // 128 keys per iteration; same for all 8
    int cnt[SORT_GPW];
#pragma unroll
    for (int g = 0; g < SORT_GPW; ++g) cnt[g] = 0;

#pragma unroll 2
    for (int t = 0; t < tb; ++t) {                 // all j < i : kj <= ki
        const uint4 k = k4[t * 32 + lane];
#pragma unroll
        for (int g = 0; g < SORT_GPW; ++g) {
            cnt[g] += (k.x <= ki[g]);
            cnt[g] += (k.y <= ki[g]);
            cnt[g] += (k.z <= ki[g]);
            cnt[g] += (k.w <= ki[g]);
        }
    }
    {   // boundary iteration: full composite comparator on (key, index)
        const uint4 k = k4[tb * 32 + lane];
        const int j = (tb * 32 + lane) * 4;
#pragma unroll
        for (int g = 0; g < SORT_GPW; ++g) {
            const int i = i0 + g;
            cnt[g] += (k.x < ki[g]) || ((k.x == ki[g]) && (j     < i));
            cnt[g] += (k.y < ki[g]) || ((k.y == ki[g]) && (j + 1 < i));
            cnt[g] += (k.z < ki[g]) || ((k.z == ki[g]) && (j + 2 < i));
            cnt[g] += (k.w < ki[g]) || ((k.w == ki[g]) && (j + 3 < i));
        }
    }
#pragma unroll 2
    for (int t = tb + 1; t < G_N / 128; ++t) {     // all j > i : kj < ki
        const uint4 k = k4[t * 32 + lane];
#pragma unroll
        for (int g = 0; g < SORT_GPW; ++g) {
            cnt[g] += (k.x < ki[g]);
            cnt[g] += (k.y < ki[g]);
            cnt[g] += (k.z < ki[g]);
            cnt[g] += (k.w < ki[g]);
        }
    }

    int rk[SORT_GPW];
#pragma unroll
    for (int g = 0; g < SORT_GPW; ++g)
        rk[g] = __reduce_add_sync(0xffffffffu, cnt[g]);

    if (lane < SORT_GPW) {
        const int i = i0 + lane;
        int r = rk[0];
#pragma unroll
        for (int g = 1; g < SORT_GPW; ++g)
            if (lane == g) r = rk[g];

        const float mx = means2d[2 * i];
        const float my = means2d[2 * i + 1];
        const float a  = conics[3 * i];
        const float b  = conics[3 * i + 1];
        const float c  = conics[3 * i + 2];
        const float op = opac[i];

        // alpha = op*exp(-sigma) >= 1/255  <=>  sigma <= ln(255*op) = smax
        const float smax = logf(op * 255.0f);
        const float det  = a * c - b * b;

        d_A[r] = make_float4(mx, my, 0.5f * a, b);
        d_B[r] = make_float4(0.5f * c, smax, op, colors[3 * i]);
        d_C[r] = make_float2(colors[3 * i + 1], colors[3 * i + 2]);

        float4 bb;
        if (smax > 0.0f && det > 0.0f) {
            const float rx = sqrtf(fmaxf(0.0f, 2.0f * smax * c / det)) * 1.001f + 0.01f;
            const float ry = sqrtf(fmaxf(0.0f, 2.0f * smax * a / det)) * 1.001f + 0.01f;
            bb = make_float4(mx - rx, my - ry, mx + rx, my + ry);
        } else {
            bb = make_float4(1e9f, 1e9f, -1e9f, -1e9f);
        }
        d_bbox[r] = bb;
    }
}

// ---------------------------------------------------------------------------
// Exact (conservative) ellipse-vs-rect: keep iff min over rect of
// sigma(p) = A2*dx^2 + b*dx*dy + C2*dy^2 is <= smax (+margin).
// ---------------------------------------------------------------------------
__device__ __forceinline__ bool ellipse_hits_rect(
    float mx, float my, float A2, float b, float C2, float smax,
    float X0, float X1, float Y0, float Y1)
{
    if (mx >= X0 && mx <= X1 && my >= Y0 && my <= Y1) return true;
    const float dx0 = X0 - mx, dx1 = X1 - mx;
    const float dy0 = Y0 - my, dy1 = Y1 - my;
    const float fy = __fdividef(-b, 2.0f * C2);
    const float fx = __fdividef(-b, 2.0f * A2);

    float q = 3.4e38f;
    {   const float y = fminf(fmaxf(fy * dx0, dy0), dy1);
        q = fminf(q, A2 * dx0 * dx0 + b * dx0 * y + C2 * y * y); }
    {   const float y = fminf(fmaxf(fy * dx1, dy0), dy1);
        q = fminf(q, A2 * dx1 * dx1 + b * dx1 * y + C2 * y * y); }
    {   const float x = fminf(fmaxf(fx * dy0, dx0), dx1);
        q = fminf(q, A2 * x * x + b * x * dy0 + C2 * dy0 * dy0); }
    {   const float x = fminf(fmaxf(fx * dy1, dx0), dx1);
        q = fminf(q, A2 * x * x + b * x * dy1 + C2 * dy1 * dy1); }
    return q <= smax + 1e-2f;    // conservative margin (over-keep only)
}

// ---------------------------------------------------------------------------
// Kernel 2: binning. 8 lanes per gaussian (4 gaussians/warp); lanes split the
// covered tile range. atomicOr is order-independent -> deterministic.
// ---------------------------------------------------------------------------
__global__ __launch_bounds__(TPB) void binning_kernel()
{
    const int r   = (blockIdx.x * (TPB / 32) + (threadIdx.x >> 5)) * 4
                  + ((threadIdx.x >> 3) & 3);
    const int sub = threadIdx.x & 7;

    const float4 bb = d_bbox[r];
    if (bb.x > bb.z) return;

    const int tx0 = max(0, __float2int_rd((bb.x - 0.5f) * (1.0f / 16.0f)));
    const int tx1 = min(TX_N - 1, __float2int_rd((bb.z - 0.5f) * (1.0f / 16.0f)));
    const int ty0 = max(0, __float2int_rd((bb.y - 0.5f) * (1.0f / 16.0f)));
    const int ty1 = min(TY_N - 1, __float2int_rd((bb.w - 0.5f) * (1.0f / 16.0f)));
    if (tx1 < tx0 || ty1 < ty0) return;

    const int W = tx1 - tx0 + 1;
    const int n = W * (ty1 - ty0 + 1);

    const float4 A = d_A[r];    // mx, my, a/2, b
    const float4 B = d_B[r];    // c/2, smax, op, col.r

    for (int t = sub; t < n; t += 8) {
        const int tx = tx0 + t % W;
        const int ty = ty0 + t / W;
        const float X0 = (float)(tx * TILE) + 0.5f;
        const float Y0 = (float)(ty * TILE) + 0.5f;
        if (ellipse_hits_rect(A.x, A.y, A.z, A.w, B.x, B.y,
                              X0, X0 + (float)(TILE - 1),
                              Y0, Y0 + (float)(TILE - 1))) {
            const int tile = ty * TX_N + tx;
            atomicOr(&d_bits[tile * NWORDS + (r >> 5)], 1u << (r & 31));
        }
    }
}

// ---------------------------------------------------------------------------
// Kernel 3: raster (R11 configuration — frozen). One 16x16 tile per block,
// 256 threads, 1 px/thread.
// Phase 1: bitmap -> compact uint16 rank list (ascending rank == depth order).
// Phase 2: 512-entry chunks staged to smem, composite from broadcast LDS;
// warp exits via __all_sync when all its 32 pixels reach T < 1e-4 (exact).
// ---------------------------------------------------------------------------
__global__ __launch_bounds__(TPB) void raster_kernel(float* __restrict__ out)
{
    const int tileX = blockIdx.x, tileY = blockIdx.y;
    const int tileI = tileY * TX_N + tileX;
    const int tid   = threadIdx.x;
    const int warp  = tid >> 5, lane = tid & 31;
    const float px  = (float)(tileX * TILE + (tid & (TILE - 1))) + 0.5f;
    const float py  = (float)(tileY * TILE + (tid >> 4)) + 0.5f;

    __shared__ unsigned short s_list[G_N];   // 16 KB
    __shared__ float4 s_A[CH];               // 8 KB
    __shared__ float4 s_B[CH];               // 8 KB
    __shared__ float2 s_C[CH];               // 4 KB
    __shared__ int s_wsum[8];
    __shared__ int s_cnt;

    // ---- Phase 1: build list ----
    const unsigned w = d_bits[tileI * NWORDS + tid];
    const int c = __popc(w);

    int incl = c;
#pragma unroll
    for (int o = 1; o < 32; o <<= 1) {
        const int v = __shfl_up_sync(0xffffffffu, incl, o);
        if (lane >= o) incl += v;
    }
    if (lane == 31) s_wsum[warp] = incl;
    __syncthreads();
    int base = 0;
#pragma unroll
    for (int k = 0; k < 8; ++k)
        if (k < warp) base += s_wsum[k];
    if (tid == 0) {
        int tot = 0;
#pragma unroll
        for (int k = 0; k < 8; ++k) tot += s_wsum[k];
        s_cnt = tot;
    }
    int ofs = base + incl - c;
    unsigned bits = w;
    const int rbase = tid << 5;
    while (bits) {
        const int rb = __ffs(bits) - 1;
        bits &= bits - 1;
        s_list[ofs++] = (unsigned short)(rbase + rb);
    }
    __syncthreads();
    const int cnt = s_cnt;

    // ---- Phase 2: chunked stage + composite ----
    float T = 1.0f;
    float aR = 0.0f, aG = 0.0f, aB = 0.0f;
    bool done = false;

    for (int c0 = 0; c0 < cnt; c0 += CH) {
        const int n = min(CH, cnt - c0);
        for (int k = tid; k < n; k += TPB) {
            const int r = s_list[c0 + k];
            s_A[k] = d_A[r];
            s_B[k] = d_B[r];
            s_C[k] = d_C[r];
        }
        __syncthreads();

#pragma unroll 1
        for (int j = 0; j < n; ++j) {
            if (!done) {
                const float4 A = s_A[j];       // broadcast LDS
                const float4 B = s_B[j];
                const float dx = px - A.x;
                const float dy = py - A.y;
                const float sg = fmaf(A.z * dx, dx,
                                 fmaf(B.x * dy, dy, A.w * dx * dy));
                if (sg >= 0.0f && sg <= B.y) {
                    const float2 C = s_C[j];
                    const float alpha = fminf(0.99f, B.z * __expf(-sg));
                    const float wgt = alpha * T;
                    aR += wgt * B.w; aG += wgt * C.x; aB += wgt * C.y;
                    T *= (1.0f - alpha);
                    done = (T < 1e-4f);
                }
            }
            if (__all_sync(0xffffffffu, done)) break;
        }
        __syncthreads();   // chunk consumed before restaging
    }

    float* o = out + ((size_t)(tileY * TILE + (tid >> 4)) * IMG_W
                      + (tileX * TILE + (tid & (TILE - 1)))) * 3;
    o[0] = aR;
    o[1] = aG;
    o[2] = aB;
}

// ---------------------------------------------------------------------------
extern "C" void kernel_launch(void* const* d_in, const int* in_sizes, int n_in,
                              void* d_out, int out_size)
{
    const float* means2d   = (const float*)d_in[0];
    const float* conics    = (const float*)d_in[1];
    const float* colors    = (const float*)d_in[2];
    const float* opacities = (const float*)d_in[3];
    const float* depths    = (const float*)d_in[4];
    float* out = (float*)d_out;

    sort_gather_kernel<<<SORT_BLOCKS, SORT_TPB>>>(means2d, conics, colors, opacities, depths);
    binning_kernel<<<G_N / ((TPB / 32) * 4), TPB>>>();
    dim3 grid(TX_N, TY_N);
    raster_kernel<<<grid, TPB>>>(out);
}

// round 16
// speedup vs baseline: 1.8529x; 1.1663x over previous
#include <cuda_runtime.h>

#define G_N 8192
#define IMG_W 512
#define IMG_H 512
#define TILE 16
#define TX_N (IMG_W / TILE)       // 32
#define TY_N (IMG_H / TILE)       // 32
#define N_TILES (TX_N * TY_N)     // 1024
#define NWORDS (G_N / 32)         // 256 bitmap words per tile
#define TPB 256
#define CH 512                    // raster staging chunk (entries)
#define SORT_TPB 128              // 4 warps
#define SORT_GPW 8                // gaussians ranked per warp
#define SORT_BLOCKS (G_N / ((SORT_TPB / 32) * SORT_GPW))   // 256

// Sorted (by depth) gaussian data, raster-ready layout.
__device__ float4 d_A[G_N];              // mx, my, 0.5*a, b
__device__ float4 d_B[G_N];              // 0.5*c, sigma_max=ln(255*op), op, col.r
__device__ float2 d_C[G_N];              // col.g, col.b
// Per-tile rank bitmaps: bit r set => sorted gaussian r overlaps the tile.
// Cleared by raster_kernel at the END of each launch (read-then-zero), so
// every launch starts clean (zero at module load; replay-invariant).
__device__ unsigned d_bits[N_TILES * NWORDS];   // 1 MB

// ---------------------------------------------------------------------------
// Exact (conservative) ellipse-vs-rect: keep iff min over rect of
// sigma(p) = A2*dx^2 + b*dx*dy + C2*dy^2 is <= smax (+margin).
// ---------------------------------------------------------------------------
__device__ __forceinline__ bool ellipse_hits_rect(
    float mx, float my, float A2, float b, float C2, float smax,
    float X0, float X1, float Y0, float Y1)
{
    if (mx >= X0 && mx <= X1 && my >= Y0 && my <= Y1) return true;
    const float dx0 = X0 - mx, dx1 = X1 - mx;
    const float dy0 = Y0 - my, dy1 = Y1 - my;
    const float fy = __fdividef(-b, 2.0f * C2);
    const float fx = __fdividef(-b, 2.0f * A2);

    float q = 3.4e38f;
    {   const float y = fminf(fmaxf(fy * dx0, dy0), dy1);
        q = fminf(q, A2 * dx0 * dx0 + b * dx0 * y + C2 * y * y); }
    {   const float y = fminf(fmaxf(fy * dx1, dy0), dy1);
        q = fminf(q, A2 * dx1 * dx1 + b * dx1 * y + C2 * y * y); }
    {   const float x = fminf(fmaxf(fx * dy0, dx0), dx1);
        q = fminf(q, A2 * x * x + b * x * dy0 + C2 * dy0 * dy0); }
    {   const float x = fminf(fmaxf(fx * dy1, dx0), dx1);
        q = fminf(q, A2 * x * x + b * x * dy1 + C2 * dy1 * dy1); }
    return q <= smax + 1e-2f;    // conservative margin (over-keep only)
}

// ---------------------------------------------------------------------------
// Kernel 1: stable rank-sort by depth + gather + INLINE BINNING.
// LDG-streaming rank (R15): each warp ranks 8 gaussians; lanes stream all
// keys via uint4 LDG. i0 is 8-aligned -> all 8 targets in boundary block
// tb = i0>>7. Split comparator (t<tb: kj<=ki ; t>tb: kj<ki ; t==tb: full
// composite on (key, index)) reproduces argsort(stable=True) exactly.
// Then lanes 0-7 compute params/bbox; the warp broadcasts each gaussian via
// shfl and all 32 lanes split its tile footprint (exact ellipse-rect test +
// atomicOr into the per-tile rank bitmap). atomicOr order-independent ->
// deterministic. Bitmap was cleared by the previous launch's raster.
// ---------------------------------------------------------------------------
__global__ __launch_bounds__(SORT_TPB) void sort_gather_bin_kernel(
    const float* __restrict__ means2d,
    const float* __restrict__ conics,
    const float* __restrict__ colors,
    const float* __restrict__ opac,
    const float* __restrict__ depths)
{
    const int tid  = threadIdx.x;
    const int warp = tid >> 5, lane = tid & 31;
    const unsigned FULL = 0xffffffffu;

    const unsigned* ku = (const unsigned*)depths;
    const uint4*    k4 = (const uint4*)depths;

    const int i0 = (blockIdx.x * (SORT_TPB / 32) + warp) * SORT_GPW;
    unsigned ki[SORT_GPW];
#pragma unroll
    for (int g = 0; g < SORT_GPW; ++g) ki[g] = ku[i0 + g];

    const int tb = i0 >> 7;          // 128 keys per iteration; same for all 8
    int cnt[SORT_GPW];
#pragma unroll
    for (int g = 0; g < SORT_GPW; ++g) cnt[g] = 0;

#pragma unroll 2
    for (int t = 0; t < tb; ++t) {                 // all j < i : kj <= ki
        const uint4 k = k4[t * 32 + lane];
#pragma unroll
        for (int g = 0; g < SORT_GPW; ++g) {
            cnt[g] += (k.x <= ki[g]);
            cnt[g] += (k.y <= ki[g]);
            cnt[g] += (k.z <= ki[g]);
            cnt[g] += (k.w <= ki[g]);
        }
    }
    {   // boundary iteration: full composite comparator on (key, index)
        const uint4 k = k4[tb * 32 + lane];
        const int j = (tb * 32 + lane) * 4;
#pragma unroll
        for (int g = 0; g < SORT_GPW; ++g) {
            const int i = i0 + g;
            cnt[g] += (k.x < ki[g]) || ((k.x == ki[g]) && (j     < i));
            cnt[g] += (k.y < ki[g]) || ((k.y == ki[g]) && (j + 1 < i));
            cnt[g] += (k.z < ki[g]) || ((k.z == ki[g]) && (j + 2 < i));
            cnt[g] += (k.w < ki[g]) || ((k.w == ki[g]) && (j + 3 < i));
        }
    }
#pragma unroll 2
    for (int t = tb + 1; t < G_N / 128; ++t) {     // all j > i : kj < ki
        const uint4 k = k4[t * 32 + lane];
#pragma unroll
        for (int g = 0; g < SORT_GPW; ++g) {
            cnt[g] += (k.x < ki[g]);
            cnt[g] += (k.y < ki[g]);
            cnt[g] += (k.z < ki[g]);
            cnt[g] += (k.w < ki[g]);
        }
    }

    int rk[SORT_GPW];
#pragma unroll
    for (int g = 0; g < SORT_GPW; ++g)
        rk[g] = __reduce_add_sync(FULL, cnt[g]);

    // ---- gather (lanes 0-7, one gaussian each) ----
    float4 bb = make_float4(1e9f, 1e9f, -1e9f, -1e9f);
    float mx = 0.f, my = 0.f, ha = 0.f, bc = 0.f, hc = 0.f, smax = -1.f;
    int r = 0;

    if (lane < SORT_GPW) {
        const int i = i0 + lane;
#pragma unroll
        for (int g = 0; g < SORT_GPW; ++g)
            if (lane == g) r = rk[g];

        mx = means2d[2 * i];
        my = means2d[2 * i + 1];
        const float a = conics[3 * i];
        const float b = conics[3 * i + 1];
        const float c = conics[3 * i + 2];
        const float op = opac[i];

        // alpha = op*exp(-sigma) >= 1/255  <=>  sigma <= ln(255*op) = smax
        smax = logf(op * 255.0f);
        const float det = a * c - b * b;
        ha = 0.5f * a; bc = b; hc = 0.5f * c;

        d_A[r] = make_float4(mx, my, ha, bc);
        d_B[r] = make_float4(hc, smax, op, colors[3 * i]);
        d_C[r] = make_float2(colors[3 * i + 1], colors[3 * i + 2]);

        if (smax > 0.0f && det > 0.0f) {
            const float rx = sqrtf(fmaxf(0.0f, 2.0f * smax * c / det)) * 1.001f + 0.01f;
            const float ry = sqrtf(fmaxf(0.0f, 2.0f * smax * a / det)) * 1.001f + 0.01f;
            bb = make_float4(mx - rx, my - ry, mx + rx, my + ry);
        }
    }

    // ---- inline binning: warp processes its 8 gaussians ----
#pragma unroll 1
    for (int g = 0; g < SORT_GPW; ++g) {
        const float gx0 = __shfl_sync(FULL, bb.x, g);
        const float gx1 = __shfl_sync(FULL, bb.z, g);
        if (gx0 > gx1) continue;                       // empty (warp-uniform)
        const float gy0 = __shfl_sync(FULL, bb.y, g);
        const float gy1 = __shfl_sync(FULL, bb.w, g);

        const int tx0 = max(0, __float2int_rd((gx0 - 0.5f) * (1.0f / 16.0f)));
        const int tx1 = min(TX_N - 1, __float2int_rd((gx1 - 0.5f) * (1.0f / 16.0f)));
        const int ty0 = max(0, __float2int_rd((gy0 - 0.5f) * (1.0f / 16.0f)));
        const int ty1 = min(TY_N - 1, __float2int_rd((gy1 - 0.5f) * (1.0f / 16.0f)));
        if (tx1 < tx0 || ty1 < ty0) continue;          // warp-uniform

        const float gmx = __shfl_sync(FULL, mx, g);
        const float gmy = __shfl_sync(FULL, my, g);
        const float gha = __shfl_sync(FULL, ha, g);
        const float gbc = __shfl_sync(FULL, bc, g);
        const float ghc = __shfl_sync(FULL, hc, g);
        const float gsm = __shfl_sync(FULL, smax, g);
        const int   gr  = __shfl_sync(FULL, r, g);

        const int W = tx1 - tx0 + 1;
        const int n = W * (ty1 - ty0 + 1);
        for (int t = lane; t < n; t += 32) {
            const int tx = tx0 + t % W;
            const int ty = ty0 + t / W;
            const float X0 = (float)(tx * TILE) + 0.5f;
            const float Y0 = (float)(ty * TILE) + 0.5f;
            if (ellipse_hits_rect(gmx, gmy, gha, gbc, ghc, gsm,
                                  X0, X0 + (float)(TILE - 1),
                                  Y0, Y0 + (float)(TILE - 1))) {
                const int tile = ty * TX_N + tx;
                atomicOr(&d_bits[tile * NWORDS + (gr >> 5)], 1u << (gr & 31));
            }
        }
    }
}

// ---------------------------------------------------------------------------
// Kernel 2: raster. One 16x16 tile per block, 256 threads, 1 px/thread.
// Phase 1: bitmap -> compact uint16 rank list (ascending rank == depth
// order); each thread ZEROES its bitmap word right after reading it, leaving
// d_bits clean for the next launch/replay.
// Phase 2: 512-entry chunks staged to smem, padded to a multiple of 8 with
// sentinel entries (smax = -1: can never pass). Inner loop unrolled 8x with
// ONE __all_sync exit vote per 8 ranks (<=7 cheap wasted iterations; exit
// at T < 1e-4 remains exact -- later weights are exactly zero).
// ---------------------------------------------------------------------------
__global__ __launch_bounds__(TPB) void raster_kernel(float* __restrict__ out)
{
    const int tileX = blockIdx.x, tileY = blockIdx.y;
    const int tileI = tileY * TX_N + tileX;
    const int tid   = threadIdx.x;
    const int warp  = tid >> 5, lane = tid & 31;
    const float px  = (float)(tileX * TILE + (tid & (TILE - 1))) + 0.5f;
    const float py  = (float)(tileY * TILE + (tid >> 4)) + 0.5f;
    const unsigned FULL = 0xffffffffu;

    __shared__ unsigned short s_list[G_N];   // 16 KB
    __shared__ float4 s_A[CH];               // 8 KB
    __shared__ float4 s_B[CH];               // 8 KB
    __shared__ float2 s_C[CH];               // 4 KB
    __shared__ int s_wsum[8];
    __shared__ int s_cnt;

    // ---- Phase 1: build list (read then zero the bitmap word) ----
    const unsigned w = d_bits[tileI * NWORDS + tid];
    d_bits[tileI * NWORDS + tid] = 0u;       // clean for next launch
    const int c = __popc(w);

    int incl = c;
#pragma unroll
    for (int o = 1; o < 32; o <<= 1) {
        const int v = __shfl_up_sync(FULL, incl, o);
        if (lane >= o) incl += v;
    }
    if (lane == 31) s_wsum[warp] = incl;
    __syncthreads();
    int base = 0;
#pragma unroll
    for (int k = 0; k < 8; ++k)
        if (k < warp) base += s_wsum[k];
    if (tid == 0) {
        int tot = 0;
#pragma unroll
        for (int k = 0; k < 8; ++k) tot += s_wsum[k];
        s_cnt = tot;
    }
    int ofs = base + incl - c;
    unsigned bits = w;
    const int rbase = tid << 5;
    while (bits) {
        const int rb = __ffs(bits) - 1;
        bits &= bits - 1;
        s_list[ofs++] = (unsigned short)(rbase + rb);
    }
    __syncthreads();
    const int cnt = s_cnt;

    // ---- Phase 2: chunked stage + composite ----
    float T = 1.0f;
    float aR = 0.0f, aG = 0.0f, aB = 0.0f;
    bool done = false;

    for (int c0 = 0; c0 < cnt; c0 += CH) {
        const int n = min(CH, cnt - c0);
        const int npad = (n + 7) & ~7;       // <= CH
        for (int k = tid; k < n; k += TPB) {
            const int r = s_list[c0 + k];
            s_A[k] = d_A[r];
            s_B[k] = d_B[r];
            s_C[k] = d_C[r];
        }
        for (int k = n + tid; k < npad; k += TPB) {   // sentinel pad
            s_A[k] = make_float4(0.f, 0.f, 0.f, 0.f);
            s_B[k] = make_float4(0.f, -1.f, 0.f, 0.f);   // smax=-1: never passes
        }
        __syncthreads();

#pragma unroll 1
        for (int j0 = 0; j0 < npad; j0 += 8) {
#pragma unroll
            for (int jj = 0; jj < 8; ++jj) {
                const int j = j0 + jj;
                if (!done) {
                    const float4 A = s_A[j];       // broadcast LDS
                    const float4 B = s_B[j];
                    const float dx = px - A.x;
                    const float dy = py - A.y;
                    const float sg = fmaf(A.z * dx, dx,
                                     fmaf(B.x * dy, dy, A.w * dx * dy));
                    if (sg >= 0.0f && sg <= B.y) {
                        const float2 C = s_C[j];
                        const float alpha = fminf(0.99f, B.z * __expf(-sg));
                        const float wgt = alpha * T;
                        aR += wgt * B.w; aG += wgt * C.x; aB += wgt * C.y;
                        T *= (1.0f - alpha);
                        done = (T < 1e-4f);
                    }
                }
            }
            if (__all_sync(FULL, done)) break;
        }
        __syncthreads();   // chunk consumed before restaging
    }

    float* o = out + ((size_t)(tileY * TILE + (tid >> 4)) * IMG_W
                      + (tileX * TILE + (tid & (TILE - 1)))) * 3;
    o[0] = aR;
    o[1] = aG;
    o[2] = aB;
}

// ---------------------------------------------------------------------------
extern "C" void kernel_launch(void* const* d_in, const int* in_sizes, int n_in,
                              void* d_out, int out_size)
{
    const float* means2d   = (const float*)d_in[0];
    const float* conics    = (const float*)d_in[1];
    const float* colors    = (const float*)d_in[2];
    const float* opacities = (const float*)d_in[3];
    const float* depths    = (const float*)d_in[4];
    float* out = (float*)d_out;

    sort_gather_bin_kernel<<<SORT_BLOCKS, SORT_TPB>>>(means2d, conics, colors, opacities, depths);
    dim3 grid(TX_N, TY_N);
    raster_kernel<<<grid, TPB>>>(out);
}

// round 17
// speedup vs baseline: 1.9115x; 1.0316x over previous
#include <cuda_runtime.h>

#define G_N 8192
#define IMG_W 512
#define IMG_H 512
#define TILE 16
#define TX_N (IMG_W / TILE)       // 32
#define TY_N (IMG_H / TILE)       // 32
#define N_TILES (TX_N * TY_N)     // 1024
#define NWORDS (G_N / 32)         // 256 bitmap words per tile
#define TPB 256
#define CH 256                    // raster staging chunk (entries)
#define SORT_TPB 128              // 4 warps
#define SORT_GPW 8                // gaussians ranked per warp
#define SORT_BLOCKS (G_N / ((SORT_TPB / 32) * SORT_GPW))   // 256

// Sorted (by depth) gaussian data, raster-ready layout.
__device__ float4 d_A[G_N];              // mx, my, 0.5*a, b
__device__ float4 d_B[G_N];              // 0.5*c, sigma_max=ln(255*op), op, col.r
__device__ float2 d_C[G_N];              // col.g, col.b
// Per-tile rank bitmaps: bit r set => sorted gaussian r overlaps the tile.
// Cleared by raster_kernel (read-then-zero), so every launch starts clean
// (zero at module load; replay-invariant).
__device__ unsigned d_bits[N_TILES * NWORDS];   // 1 MB

// ---------------------------------------------------------------------------
// Exact (conservative) ellipse-vs-rect: keep iff min over rect of
// sigma(p) = A2*dx^2 + b*dx*dy + C2*dy^2 is <= smax (+margin).
// ---------------------------------------------------------------------------
__device__ __forceinline__ bool ellipse_hits_rect(
    float mx, float my, float A2, float b, float C2, float smax,
    float X0, float X1, float Y0, float Y1)
{
    if (mx >= X0 && mx <= X1 && my >= Y0 && my <= Y1) return true;
    const float dx0 = X0 - mx, dx1 = X1 - mx;
    const float dy0 = Y0 - my, dy1 = Y1 - my;
    const float fy = __fdividef(-b, 2.0f * C2);
    const float fx = __fdividef(-b, 2.0f * A2);

    float q = 3.4e38f;
    {   const float y = fminf(fmaxf(fy * dx0, dy0), dy1);
        q = fminf(q, A2 * dx0 * dx0 + b * dx0 * y + C2 * y * y); }
    {   const float y = fminf(fmaxf(fy * dx1, dy0), dy1);
        q = fminf(q, A2 * dx1 * dx1 + b * dx1 * y + C2 * y * y); }
    {   const float x = fminf(fmaxf(fx * dy0, dx0), dx1);
        q = fminf(q, A2 * x * x + b * x * dy0 + C2 * dy0 * dy0); }
    {   const float x = fminf(fmaxf(fx * dy1, dx0), dx1);
        q = fminf(q, A2 * x * x + b * x * dy1 + C2 * dy1 * dy1); }
    return q <= smax + 1e-2f;    // conservative margin (over-keep only)
}

// ---------------------------------------------------------------------------
// Kernel 1: stable rank-sort by depth + gather + inline binning (frozen from
// R16, measured 13.6us combined with launch overhead).
// ---------------------------------------------------------------------------
__global__ __launch_bounds__(SORT_TPB) void sort_gather_bin_kernel(
    const float* __restrict__ means2d,
    const float* __restrict__ conics,
    const float* __restrict__ colors,
    const float* __restrict__ opac,
    const float* __restrict__ depths)
{
    const int tid  = threadIdx.x;
    const int warp = tid >> 5, lane = tid & 31;
    const unsigned FULL = 0xffffffffu;

    const unsigned* ku = (const unsigned*)depths;
    const uint4*    k4 = (const uint4*)depths;

    const int i0 = (blockIdx.x * (SORT_TPB / 32) + warp) * SORT_GPW;
    unsigned ki[SORT_GPW];
#pragma unroll
    for (int g = 0; g < SORT_GPW; ++g) ki[g] = ku[i0 + g];

    const int tb = i0 >> 7;          // 128 keys per iteration; same for all 8
    int cnt[SORT_GPW];
#pragma unroll
    for (int g = 0; g < SORT_GPW; ++g) cnt[g] = 0;

#pragma unroll 2
    for (int t = 0; t < tb; ++t) {                 // all j < i : kj <= ki
        const uint4 k = k4[t * 32 + lane];
#pragma unroll
        for (int g = 0; g < SORT_GPW; ++g) {
            cnt[g] += (k.x <= ki[g]);
            cnt[g] += (k.y <= ki[g]);
            cnt[g] += (k.z <= ki[g]);
            cnt[g] += (k.w <= ki[g]);
        }
    }
    {   // boundary iteration: full composite comparator on (key, index)
        const uint4 k = k4[tb * 32 + lane];
        const int j = (tb * 32 + lane) * 4;
#pragma unroll
        for (int g = 0; g < SORT_GPW; ++g) {
            const int i = i0 + g;
            cnt[g] += (k.x < ki[g]) || ((k.x == ki[g]) && (j     < i));
            cnt[g] += (k.y < ki[g]) || ((k.y == ki[g]) && (j + 1 < i));
            cnt[g] += (k.z < ki[g]) || ((k.z == ki[g]) && (j + 2 < i));
            cnt[g] += (k.w < ki[g]) || ((k.w == ki[g]) && (j + 3 < i));
        }
    }
#pragma unroll 2
    for (int t = tb + 1; t < G_N / 128; ++t) {     // all j > i : kj < ki
        const uint4 k = k4[t * 32 + lane];
#pragma unroll
        for (int g = 0; g < SORT_GPW; ++g) {
            cnt[g] += (k.x < ki[g]);
            cnt[g] += (k.y < ki[g]);
            cnt[g] += (k.z < ki[g]);
            cnt[g] += (k.w < ki[g]);
        }
    }

    int rk[SORT_GPW];
#pragma unroll
    for (int g = 0; g < SORT_GPW; ++g)
        rk[g] = __reduce_add_sync(FULL, cnt[g]);

    // ---- gather (lanes 0-7, one gaussian each) ----
    float4 bb = make_float4(1e9f, 1e9f, -1e9f, -1e9f);
    float mx = 0.f, my = 0.f, ha = 0.f, bc = 0.f, hc = 0.f, smax = -1.f;
    int r = 0;

    if (lane < SORT_GPW) {
        const int i = i0 + lane;
#pragma unroll
        for (int g = 0; g < SORT_GPW; ++g)
            if (lane == g) r = rk[g];

        mx = means2d[2 * i];
        my = means2d[2 * i + 1];
        const float a = conics[3 * i];
        const float b = conics[3 * i + 1];
        const float c = conics[3 * i + 2];
        const float op = opac[i];

        // alpha = op*exp(-sigma) >= 1/255  <=>  sigma <= ln(255*op) = smax
        smax = logf(op * 255.0f);
        const float det = a * c - b * b;
        ha = 0.5f * a; bc = b; hc = 0.5f * c;

        d_A[r] = make_float4(mx, my, ha, bc);
        d_B[r] = make_float4(hc, smax, op, colors[3 * i]);
        d_C[r] = make_float2(colors[3 * i + 1], colors[3 * i + 2]);

        if (smax > 0.0f && det > 0.0f) {
            const float rx = sqrtf(fmaxf(0.0f, 2.0f * smax * c / det)) * 1.001f + 0.01f;
            const float ry = sqrtf(fmaxf(0.0f, 2.0f * smax * a / det)) * 1.001f + 0.01f;
            bb = make_float4(mx - rx, my - ry, mx + rx, my + ry);
        }
    }

    // ---- inline binning: warp processes its 8 gaussians ----
#pragma unroll 1
    for (int g = 0; g < SORT_GPW; ++g) {
        const float gx0 = __shfl_sync(FULL, bb.x, g);
        const float gx1 = __shfl_sync(FULL, bb.z, g);
        if (gx0 > gx1) continue;                       // empty (warp-uniform)
        const float gy0 = __shfl_sync(FULL, bb.y, g);
        const float gy1 = __shfl_sync(FULL, bb.w, g);

        const int tx0 = max(0, __float2int_rd((gx0 - 0.5f) * (1.0f / 16.0f)));
        const int tx1 = min(TX_N - 1, __float2int_rd((gx1 - 0.5f) * (1.0f / 16.0f)));
        const int ty0 = max(0, __float2int_rd((gy0 - 0.5f) * (1.0f / 16.0f)));
        const int ty1 = min(TY_N - 1, __float2int_rd((gy1 - 0.5f) * (1.0f / 16.0f)));
        if (tx1 < tx0 || ty1 < ty0) continue;          // warp-uniform

        const float gmx = __shfl_sync(FULL, mx, g);
        const float gmy = __shfl_sync(FULL, my, g);
        const float gha = __shfl_sync(FULL, ha, g);
        const float gbc = __shfl_sync(FULL, bc, g);
        const float ghc = __shfl_sync(FULL, hc, g);
        const float gsm = __shfl_sync(FULL, smax, g);
        const int   gr  = __shfl_sync(FULL, r, g);

        const int W = tx1 - tx0 + 1;
        const int n = W * (ty1 - ty0 + 1);
        for (int t = lane; t < n; t += 32) {
            const int tx = tx0 + t % W;
            const int ty = ty0 + t / W;
            const float X0 = (float)(tx * TILE) + 0.5f;
            const float Y0 = (float)(ty * TILE) + 0.5f;
            if (ellipse_hits_rect(gmx, gmy, gha, gbc, ghc, gsm,
                                  X0, X0 + (float)(TILE - 1),
                                  Y0, Y0 + (float)(TILE - 1))) {
                const int tile = ty * TX_N + tx;
                atomicOr(&d_bits[tile * NWORDS + (gr >> 5)], 1u << (gr & 31));
            }
        }
    }
}

// ---------------------------------------------------------------------------
// Kernel 2: raster. One 16x16 tile per block, 256 threads, 1 px/thread.
// Warp -> compact 8x4 pixel subtile (was 16x2 strip): transmittance is
// spatially smooth, so a compact footprint has more correlated done-times
// -> shorter warp-exit tail. __launch_bounds__(256,6) + CH=256 raise
// residency to 6 CTAs/SM.
// Phase 1: bitmap -> compact uint16 rank list (ascending rank == depth
// order); each thread zeroes its bitmap word right after reading it.
// Phase 2: 256-entry chunks staged to smem, padded to a multiple of 8 with
// sentinels (smax=-1, never pass); 8x-unrolled loop, one __all_sync vote
// per 8 ranks. Exit at T < 1e-4 is exact (later weights exactly zero).
// ---------------------------------------------------------------------------
__global__ __launch_bounds__(TPB, 6) void raster_kernel(float* __restrict__ out)
{
    const int tileX = blockIdx.x, tileY = blockIdx.y;
    const int tileI = tileY * TX_N + tileX;
    const int tid   = threadIdx.x;
    const int warp  = tid >> 5, lane = tid & 31;
    const unsigned FULL = 0xffffffffu;

    // warp -> 8x4 subtile: subtile grid 2x4 (x: 0..1, y: 0..3)
    const int lx = ((warp & 1) << 3) | (lane & 7);     // 0..15
    const int ly = ((warp >> 1) << 2) | (lane >> 3);   // 0..15
    const float px = (float)(tileX * TILE + lx) + 0.5f;
    const float py = (float)(tileY * TILE + ly) + 0.5f;

    __shared__ unsigned short s_list[G_N];   // 16 KB
    __shared__ float4 s_A[CH];               // 4 KB
    __shared__ float4 s_B[CH];               // 4 KB
    __shared__ float2 s_C[CH];               // 2 KB
    __shared__ int s_wsum[8];
    __shared__ int s_cnt;

    // ---- Phase 1: build list (read then zero the bitmap word) ----
    const unsigned w = d_bits[tileI * NWORDS + tid];
    d_bits[tileI * NWORDS + tid] = 0u;       // clean for next launch
    const int c = __popc(w);

    int incl = c;
#pragma unroll
    for (int o = 1; o < 32; o <<= 1) {
        const int v = __shfl_up_sync(FULL, incl, o);
        if (lane >= o) incl += v;
    }
    if (lane == 31) s_wsum[warp] = incl;
    __syncthreads();
    int base = 0;
#pragma unroll
    for (int k = 0; k < 8; ++k)
        if (k < warp) base += s_wsum[k];
    if (tid == 0) {
        int tot = 0;
#pragma unroll
        for (int k = 0; k < 8; ++k) tot += s_wsum[k];
        s_cnt = tot;
    }
    int ofs = base + incl - c;
    unsigned bits = w;
    const int rbase = tid << 5;
    while (bits) {
        const int rb = __ffs(bits) - 1;
        bits &= bits - 1;
        s_list[ofs++] = (unsigned short)(rbase + rb);
    }
    __syncthreads();
    const int cnt = s_cnt;

    // ---- Phase 2: chunked stage + composite ----
    float T = 1.0f;
    float aR = 0.0f, aG = 0.0f, aB = 0.0f;
    bool done = false;

    for (int c0 = 0; c0 < cnt; c0 += CH) {
        const int n = min(CH, cnt - c0);
        const int npad = (n + 7) & ~7;       // <= CH
        for (int k = tid; k < n; k += TPB) {
            const int r = s_list[c0 + k];
            s_A[k] = d_A[r];
            s_B[k] = d_B[r];
            s_C[k] = d_C[r];
        }
        for (int k = n + tid; k < npad; k += TPB) {   // sentinel pad
            s_A[k] = make_float4(0.f, 0.f, 0.f, 0.f);
            s_B[k] = make_float4(0.f, -1.f, 0.f, 0.f);   // smax=-1: never passes
        }
        __syncthreads();

#pragma unroll 1
        for (int j0 = 0; j0 < npad; j0 += 8) {
#pragma unroll
            for (int jj = 0; jj < 8; ++jj) {
                const int j = j0 + jj;
                if (!done) {
                    const float4 A = s_A[j];       // broadcast LDS
                    const float4 B = s_B[j];
                    const float dx = px - A.x;
                    const float dy = py - A.y;
                    const float sg = fmaf(A.z * dx, dx,
                                     fmaf(B.x * dy, dy, A.w * dx * dy));
                    if (sg >= 0.0f && sg <= B.y) {
                        const float2 C = s_C[j];
                        const float alpha = fminf(0.99f, B.z * __expf(-sg));
                        const float wgt = alpha * T;
                        aR += wgt * B.w; aG += wgt * C.x; aB += wgt * C.y;
                        T *= (1.0f - alpha);
                        done = (T < 1e-4f);
                    }
                }
            }
            if (__all_sync(FULL, done)) break;
        }
        __syncthreads();   // chunk consumed before restaging
    }

    float* o = out + ((size_t)(tileY * TILE + ly) * IMG_W
                      + (tileX * TILE + lx)) * 3;
    o[0] = aR;
    o[1] = aG;
    o[2] = aB;
}

// ---------------------------------------------------------------------------
extern "C" void kernel_launch(void* const* d_in, const int* in_sizes, int n_in,
                              void* d_out, int out_size)
{
    const float* means2d   = (const float*)d_in[0];
    const float* conics    = (const float*)d_in[1];
    const float* colors    = (const float*)d_in[2];
    const float* opacities = (const float*)d_in[3];
    const float* depths    = (const float*)d_in[4];
    float* out = (float*)d_out;

    sort_gather_bin_kernel<<<SORT_BLOCKS, SORT_TPB>>>(means2d, conics, colors, opacities, depths);
    dim3 grid(TX_N, TY_N);
    raster_kernel<<<grid, TPB>>>(out);
}